// round 14
// baseline (speedup 1.0000x reference)
#include <cuda_runtime.h>
#include <cuda_bf16.h>
#include <cstdint>

// Problem constants (fixed shapes)
#define NBATCH 4
#define LSEQ   8192
#define HEADS  16
#define EDIM   64
#define DDIM   64
#define CHK    128
#define NCH    64
#define NTILE  (NBATCH*HEADS*NCH)      // 4096
#define ROWSTR (HEADS*EDIM)            // 1024
#define PAY    4160                    // 4096 S (fragment-ordered) + 64 ksum

// Decoupled-lookback scan state (aggregate / inclusive / flag)
__device__ float g_agg[NTILE][PAY];    // 68 MB
__device__ float g_inc[NTILE][PAY];    // 68 MB
__device__ int   g_flag[NTILE];        // 0 = empty, 1 = aggregate, 2 = inclusive

__device__ __forceinline__ float featmap(float x) {
    return x > 0.f ? x + 1.f : __expf(x);
}
__device__ __forceinline__ uint32_t smem_u32(const void* p) {
    return (uint32_t)__cvta_generic_to_shared(p);
}
__device__ __forceinline__ uint32_t sw(uint32_t x) { return x ^ ((x >> 3) & 0x70); }

// ---- warp-level tensor core primitives --------------------------------------
__device__ __forceinline__ void mma16816(float* c, const uint32_t* a, const uint32_t* b) {
    asm volatile(
        "mma.sync.aligned.m16n8k16.row.col.f32.bf16.bf16.f32 "
        "{%0,%1,%2,%3}, {%4,%5,%6,%7}, {%8,%9}, {%0,%1,%2,%3};"
        : "+f"(c[0]), "+f"(c[1]), "+f"(c[2]), "+f"(c[3])
        : "r"(a[0]), "r"(a[1]), "r"(a[2]), "r"(a[3]), "r"(b[0]), "r"(b[1]));
}
__device__ __forceinline__ void ldsm_x4(uint32_t* r, uint32_t addr) {
    asm volatile("ldmatrix.sync.aligned.m8n8.x4.shared.b16 {%0,%1,%2,%3}, [%4];"
                 : "=r"(r[0]), "=r"(r[1]), "=r"(r[2]), "=r"(r[3]) : "r"(addr));
}
__device__ __forceinline__ void ldsm_x4t(uint32_t* r, uint32_t addr) {
    asm volatile("ldmatrix.sync.aligned.m8n8.x4.trans.shared.b16 {%0,%1,%2,%3}, [%4];"
                 : "=r"(r[0]), "=r"(r[1]), "=r"(r[2]), "=r"(r[3]) : "r"(addr));
}

// fast hi/lo split: hi = truncated-bf16 pair (one PRMT),
// lo = exact residual packed with one cvt.rn.bf16x2.f32.
__device__ __forceinline__ uint32_t pack_bf16x2(float lo, float hi) {
    uint32_t r;
    asm("cvt.rn.bf16x2.f32 %0, %1, %2;" : "=r"(r) : "f"(hi), "f"(lo));
    return r;
}
__device__ __forceinline__ void split_pack(float a, float b, uint32_t& hi, uint32_t& lo) {
    const uint32_t au = __float_as_uint(a), bu = __float_as_uint(b);
    hi = __byte_perm(au, bu, 0x7632);
    const float la = a - __uint_as_float(au & 0xFFFF0000u);
    const float lb = b - __uint_as_float(bu & 0xFFFF0000u);
    lo = pack_bf16x2(la, lb);
}
// reconstruct float from hi/lo packed pair, half = 0 (low16) or 1 (high16)
__device__ __forceinline__ float rq(uint32_t hi, uint32_t lo, int half) {
    const uint32_t hbits = half ? (hi & 0xFFFF0000u) : (hi << 16);
    const uint32_t lbits = half ? (lo & 0xFFFF0000u) : (lo << 16);
    return __uint_as_float(hbits) + __uint_as_float(lbits);
}

// ---------------------------------------------------------------------------
// Fused kernel with fragment-ordered lookback payload.
// ---------------------------------------------------------------------------
#define KH_OFF   0
#define KL_OFF   16384
#define VH_OFF   32768
#define VL_OFF   49152
#define SH_OFF   65536
#define SL_OFF   73728
#define KSC_OFF  81920
#define KSP_OFF  82176
#define FU_SMEM  82432

__global__ void __launch_bounds__(256, 2) k_fused(const float* __restrict__ Qg,
                                                  const float* __restrict__ Kg,
                                                  const float* __restrict__ Vg,
                                                  float* __restrict__ out) {
    extern __shared__ char smc[];
    const uint32_t smb = smem_u32(smc);
    float* ksC = (float*)(smc + KSC_OFF);
    float* ksP = (float*)(smc + KSP_OFF);

    const int tile = blockIdx.x;
    const int c  = tile & (NCH - 1);
    const int nh = tile >> 6;
    const int h  = nh & (HEADS - 1);
    const int n  = nh >> 4;
    const int tid = threadIdx.x;
    const int wid = tid >> 5;
    const int lid = tid & 31;

    if (tid < EDIM) ksC[tid] = 0.f;

    const size_t base = (((size_t)n * LSEQ + (size_t)c * CHK) * HEADS + h) * EDIM;

    // triangular (output) warp coords
    const int rb  = (wid < 4) ? wid : 11 - wid;
    const int m0  = rb * 16;
    const int gi  = lid & 7;
    const int grp = lid >> 3;
    const int g1  = grp & 1;
    const int q2  = grp >> 1;
    const int r0  = m0 + (lid >> 2);
    const int r1  = r0 + 8;
    // S-MMA warp coords
    const int p_mrow  = (wid & 3) * 16;
    const int p_nhalf = (wid >> 2) * 32;

    // ---- stage K (featmap, hi/lo), V (hi/lo); accumulate ksum partials ----
    float ksr[4] = {0.f, 0.f, 0.f, 0.f};
    const int c4 = (tid & 15) << 2;
    #pragma unroll
    for (int i = 0; i < 8; i++) {
        const int p   = tid + i * 256;
        const int row = p >> 4;
        const size_t g = base + (size_t)row * ROWSTR + c4;
        const float4 kv = __ldcs((const float4*)(Kg + g));
        const float4 vv = __ldcs((const float4*)(Vg + g));
        const float kf[4] = {featmap(kv.x), featmap(kv.y), featmap(kv.z), featmap(kv.w)};
        #pragma unroll
        for (int j = 0; j < 4; j++) ksr[j] += kf[j];
        const uint32_t x = sw((uint32_t)(row * 128 + c4 * 2));
        uint32_t h01, l01, h23, l23;
        split_pack(kf[0], kf[1], h01, l01);
        split_pack(kf[2], kf[3], h23, l23);
        *(uint2*)(smc + KH_OFF + x) = make_uint2(h01, h23);
        *(uint2*)(smc + KL_OFF + x) = make_uint2(l01, l23);
        split_pack(vv.x, vv.y, h01, l01);
        split_pack(vv.z, vv.w, h23, l23);
        *(uint2*)(smc + VH_OFF + x) = make_uint2(h01, h23);
        *(uint2*)(smc + VL_OFF + x) = make_uint2(l01, l23);
    }
    __syncthreads();   // bar1: K/V planes + ksC init

    // ksum_c atomics (complete by bar2)
    #pragma unroll
    for (int j = 0; j < 4; j++) {
        ksr[j] += __shfl_xor_sync(0xffffffffu, ksr[j], 16);
        if (lid < 16) atomicAdd(&ksC[c4 + j], ksr[j]);
    }

    // ---- S MMA: own S_c fragments stay in registers ----
    float C[4][4] = {};
    #pragma unroll
    for (int kk = 0; kk < CHK; kk += 16) {
        uint32_t ah[4], al[4];
        const int arow = kk + ((grp & 2) ? 8 : 0) + gi;
        const int acol = p_mrow + ((grp & 1) ? 8 : 0);
        const uint32_t ax = sw((uint32_t)(arow * 128 + acol * 2));
        ldsm_x4t(ah, smb + KH_OFF + ax);
        ldsm_x4t(al, smb + KL_OFF + ax);
        const int brow = kk + g1 * 8 + gi;
        #pragma unroll
        for (int nt = 0; nt < 4; nt += 2) {
            const uint32_t bx = sw((uint32_t)(brow * 128 + (p_nhalf + (nt + q2) * 8) * 2));
            uint32_t bh[4], bl[4];
            ldsm_x4t(bh, smb + VH_OFF + bx);
            ldsm_x4t(bl, smb + VL_OFF + bx);
            mma16816(C[nt], ah, bh);
            mma16816(C[nt], ah, bl);
            mma16816(C[nt], al, bh);
            mma16816(C[nt+1], ah, bh + 2);
            mma16816(C[nt+1], ah, bl + 2);
            mma16816(C[nt+1], al, bh + 2);
        }
    }
    __syncthreads();   // bar2: ksC atomics complete
    const float ownks = (tid < EDIM) ? ksC[tid] : 0.f;

    // ---- decoupled lookback, fragment-ordered payload ----
    float ex[4][4] = {};
    float exks = 0.f;

    if (c > 0) {
        float* A = g_agg[tile];
        #pragma unroll
        for (int nt = 0; nt < 4; nt++)
            *(float4*)&A[tid * 16 + nt * 4] =
                make_float4(C[nt][0], C[nt][1], C[nt][2], C[nt][3]);
        if (tid < EDIM) A[4096 + tid] = ownks;
        __threadfence();
        __syncthreads();
        if (tid == 0) atomicExch(&g_flag[tile], 1);

        // phase A: scan flags back to nearest inclusive (spin only on empty)
        int lo = tile - 1;
        while (true) {
            const int f = *(volatile int*)&g_flag[lo];
            if (f == 0) { __nanosleep(100); continue; }
            if (f == 2) break;
            lo--;
        }
        __threadfence();
        // phase B: parallel-sum window [lo .. tile-1]
        for (int j = tile - 1; j >= lo; j--) {
            const float* src = (j == lo) ? g_inc[j] : g_agg[j];
            #pragma unroll
            for (int nt = 0; nt < 4; nt++) {
                const float4 t = *(const float4*)&src[tid * 16 + nt * 4];
                ex[nt][0] += t.x; ex[nt][1] += t.y;
                ex[nt][2] += t.z; ex[nt][3] += t.w;
            }
            if (tid < EDIM) exks += src[4096 + tid];
        }
    }
    {   // publish inclusive ASAP (unblocks successors)
        float* I = g_inc[tile];
        #pragma unroll
        for (int nt = 0; nt < 4; nt++)
            *(float4*)&I[tid * 16 + nt * 4] =
                make_float4(ex[nt][0] + C[nt][0], ex[nt][1] + C[nt][1],
                            ex[nt][2] + C[nt][2], ex[nt][3] + C[nt][3]);
        if (tid < EDIM) I[4096 + tid] = exks + ownks;
        __threadfence();
        __syncthreads();
        if (tid == 0) atomicExch(&g_flag[tile], 2);
    }

    // ---- exclusive prefix -> S planes (split, swizzled, fragment-direct) ----
    {
        const int e0 = p_mrow + (lid >> 2);
        const int e1 = e0 + 8;
        #pragma unroll
        for (int nt = 0; nt < 4; nt++) {
            const int d = p_nhalf + nt * 8 + (lid & 3) * 2;
            uint32_t hi, lo;
            split_pack(ex[nt][0], ex[nt][1], hi, lo);
            *(uint32_t*)(smc + SH_OFF + sw((uint32_t)(e0 * 128 + d * 2))) = hi;
            *(uint32_t*)(smc + SL_OFF + sw((uint32_t)(e0 * 128 + d * 2))) = lo;
            split_pack(ex[nt][2], ex[nt][3], hi, lo);
            *(uint32_t*)(smc + SH_OFF + sw((uint32_t)(e1 * 128 + d * 2))) = hi;
            *(uint32_t*)(smc + SL_OFF + sw((uint32_t)(e1 * 128 + d * 2))) = lo;
        }
        if (tid < EDIM) ksP[tid] = exks;
    }

    // ---- build Q fragments from global (featmap + split) ----
    uint32_t aqh[4][4], aql[4][4];
    {
        const float* Q0 = Qg + base + (size_t)r0 * ROWSTR;
        const float* Q1 = Qg + base + (size_t)r1 * ROWSTR;
        const int cc = (lid & 3) * 2;
        #pragma unroll
        for (int t = 0; t < 4; t++) {
            const int c0 = t * 16 + cc;
            const float2 q00 = __ldcs((const float2*)(Q0 + c0));
            const float2 q10 = __ldcs((const float2*)(Q1 + c0));
            const float2 q01 = __ldcs((const float2*)(Q0 + c0 + 8));
            const float2 q11 = __ldcs((const float2*)(Q1 + c0 + 8));
            split_pack(featmap(q00.x), featmap(q00.y), aqh[t][0], aql[t][0]);
            split_pack(featmap(q10.x), featmap(q10.y), aqh[t][1], aql[t][1]);
            split_pack(featmap(q01.x), featmap(q01.y), aqh[t][2], aql[t][2]);
            split_pack(featmap(q11.x), featmap(q11.y), aqh[t][3], aql[t][3]);
        }
    }
    __syncthreads();   // bar3: S planes + ksP ready

    // ---- q . ksum_prefix (reconstructed from Q fragments) ----
    float rs0 = 0.f, rs1 = 0.f;
    {
        const int cc = (lid & 3) * 2;
        #pragma unroll
        for (int t = 0; t < 4; t++) {
            const int c0 = t * 16 + cc;
            const float ka = ksP[c0],     kb = ksP[c0 + 1];
            const float kc = ksP[c0 + 8], kd = ksP[c0 + 9];
            rs0 += rq(aqh[t][0], aql[t][0], 0) * ka + rq(aqh[t][0], aql[t][0], 1) * kb
                 + rq(aqh[t][2], aql[t][2], 0) * kc + rq(aqh[t][2], aql[t][2], 1) * kd;
            rs1 += rq(aqh[t][1], aql[t][1], 0) * ka + rq(aqh[t][1], aql[t][1], 1) * kb
                 + rq(aqh[t][3], aql[t][3], 0) * kc + rq(aqh[t][3], aql[t][3], 1) * kd;
        }
    }

    float C2[8][4] = {};

    // ---- triangular: for each 16-col group jg <= rb: MMA1 -> split -> MMA2 ----
    for (int jg = 0; jg <= rb; jg++) {
        float Ct[2][4] = {};
        #pragma unroll
        for (int t = 0; t < 4; t++) {
            const uint32_t bx =
                sw((uint32_t)((jg * 16 + q2 * 8 + gi) * 128 + (t * 16 + g1 * 8) * 2));
            uint32_t bh[4], bl[4];
            ldsm_x4(bh, smb + KH_OFF + bx);
            ldsm_x4(bl, smb + KL_OFF + bx);
            mma16816(Ct[0], aqh[t], bh);
            mma16816(Ct[0], aqh[t], bl);
            mma16816(Ct[0], aql[t], bh);
            mma16816(Ct[1], aqh[t], bh + 2);
            mma16816(Ct[1], aqh[t], bl + 2);
            mma16816(Ct[1], aql[t], bh + 2);
        }
        float s00 = Ct[0][0], s01 = Ct[0][1], s02 = Ct[0][2], s03 = Ct[0][3];
        float s10 = Ct[1][0], s11 = Ct[1][1], s12 = Ct[1][2], s13 = Ct[1][3];
        if (jg == rb) {   // diagonal block: causal mask
            const int cA = jg * 16 + (lid & 3) * 2;
            const int cB = cA + 8;
            s00 = (cA     <= r0) ? s00 : 0.f;
            s01 = (cA + 1 <= r0) ? s01 : 0.f;
            s02 = (cA     <= r1) ? s02 : 0.f;
            s03 = (cA + 1 <= r1) ? s03 : 0.f;
            s10 = (cB     <= r0) ? s10 : 0.f;
            s11 = (cB + 1 <= r0) ? s11 : 0.f;
            s12 = (cB     <= r1) ? s12 : 0.f;
            s13 = (cB + 1 <= r1) ? s13 : 0.f;
        }
        rs0 += s00 + s01 + s10 + s11;
        rs1 += s02 + s03 + s12 + s13;
        uint32_t a2h[4], a2l[4];
        split_pack(s00, s01, a2h[0], a2l[0]);
        split_pack(s02, s03, a2h[1], a2l[1]);
        split_pack(s10, s11, a2h[2], a2l[2]);
        split_pack(s12, s13, a2h[3], a2l[3]);
        const int brow = jg * 16 + g1 * 8 + gi;
        #pragma unroll
        for (int nt = 0; nt < 8; nt += 2) {
            const uint32_t bx = sw((uint32_t)(brow * 128 + (nt + q2) * 16));
            uint32_t bh[4], bl[4];
            ldsm_x4t(bh, smb + VH_OFF + bx);
            ldsm_x4t(bl, smb + VL_OFF + bx);
            mma16816(C2[nt], a2h, bh);
            mma16816(C2[nt], a2h, bl);
            mma16816(C2[nt], a2l, bh);
            mma16816(C2[nt+1], a2h, bh + 2);
            mma16816(C2[nt+1], a2h, bl + 2);
            mma16816(C2[nt+1], a2l, bh + 2);
        }
    }
    rs0 += __shfl_xor_sync(0xffffffffu, rs0, 1);
    rs0 += __shfl_xor_sync(0xffffffffu, rs0, 2);
    rs1 += __shfl_xor_sync(0xffffffffu, rs1, 1);
    rs1 += __shfl_xor_sync(0xffffffffu, rs1, 2);
    const float z0 = 1.f / (rs0 + 1e-6f);
    const float z1 = 1.f / (rs1 + 1e-6f);

    // ---- MMA3: C2 += Qf @ Sprefix ----
    #pragma unroll
    for (int t = 0; t < 4; t++) {
        const int brow = t * 16 + g1 * 8 + gi;
        #pragma unroll
        for (int nt = 0; nt < 8; nt += 2) {
            const uint32_t bx = sw((uint32_t)(brow * 128 + (nt + q2) * 16));
            uint32_t bh[4], bl[4];
            ldsm_x4t(bh, smb + SH_OFF + bx);
            ldsm_x4t(bl, smb + SL_OFF + bx);
            mma16816(C2[nt], aqh[t], bh);
            mma16816(C2[nt], aqh[t], bl);
            mma16816(C2[nt], aql[t], bh);
            mma16816(C2[nt+1], aqh[t], bh + 2);
            mma16816(C2[nt+1], aqh[t], bl + 2);
            mma16816(C2[nt+1], aql[t], bh + 2);
        }
    }

    // ---- epilogue: scale in regs, direct STG ----
    {
        const size_t obase = (((size_t)n * LSEQ + (size_t)c * CHK) * HEADS + h) * DDIM;
        float* O0 = out + obase + (size_t)r0 * ROWSTR;
        float* O1 = out + obase + (size_t)r1 * ROWSTR;
        const int cc = (lid & 3) * 2;
        #pragma unroll
        for (int nt = 0; nt < 8; nt++) {
            const int cb = nt * 8 + cc;
            *(float2*)(O0 + cb) = make_float2(C2[nt][0] * z0, C2[nt][1] * z0);
            *(float2*)(O1 + cb) = make_float2(C2[nt][2] * z1, C2[nt][3] * z1);
        }
    }
}

// ---------------------------------------------------------------------------
extern "C" void kernel_launch(void* const* d_in, const int* in_sizes, int n_in,
                              void* d_out, int out_size) {
    const float* Q = (const float*)d_in[0];
    const float* K = (const float*)d_in[1];
    const float* V = (const float*)d_in[2];
    float* out = (float*)d_out;

    cudaFuncSetAttribute(k_fused, cudaFuncAttributeMaxDynamicSharedMemorySize, FU_SMEM);
    k_fused<<<NTILE, 256, FU_SMEM>>>(Q, K, V, out);
}

// round 15
// speedup vs baseline: 1.0440x; 1.0440x over previous
#include <cuda_runtime.h>
#include <cuda_bf16.h>
#include <cstdint>

// Problem constants (fixed shapes)
#define NBATCH 4
#define LSEQ   8192
#define HEADS  16
#define EDIM   64
#define DDIM   64
#define CHK    128
#define NCH    64
#define NPAIR  (NBATCH*HEADS)          // 64
#define NTILE  (NBATCH*HEADS*NCH)      // 4096
#define ROWSTR (HEADS*EDIM)            // 1024
#define PAY    4160                    // 4096 S (fragment-ordered) + 64 ksum

// Decoupled-lookback scan state (aggregate / inclusive / flag), logical tile id
__device__ float g_agg[NTILE][PAY];    // 68 MB
__device__ float g_inc[NTILE][PAY];    // 68 MB
__device__ int   g_flag[NTILE];        // 0 = empty, 1 = aggregate, 2 = inclusive

__device__ __forceinline__ float featmap(float x) {
    return x > 0.f ? x + 1.f : __expf(x);
}
__device__ __forceinline__ uint32_t smem_u32(const void* p) {
    return (uint32_t)__cvta_generic_to_shared(p);
}
__device__ __forceinline__ uint32_t sw(uint32_t x) { return x ^ ((x >> 3) & 0x70); }

// ---- warp-level tensor core primitives --------------------------------------
__device__ __forceinline__ void mma16816(float* c, const uint32_t* a, const uint32_t* b) {
    asm volatile(
        "mma.sync.aligned.m16n8k16.row.col.f32.bf16.bf16.f32 "
        "{%0,%1,%2,%3}, {%4,%5,%6,%7}, {%8,%9}, {%0,%1,%2,%3};"
        : "+f"(c[0]), "+f"(c[1]), "+f"(c[2]), "+f"(c[3])
        : "r"(a[0]), "r"(a[1]), "r"(a[2]), "r"(a[3]), "r"(b[0]), "r"(b[1]));
}
__device__ __forceinline__ void ldsm_x4(uint32_t* r, uint32_t addr) {
    asm volatile("ldmatrix.sync.aligned.m8n8.x4.shared.b16 {%0,%1,%2,%3}, [%4];"
                 : "=r"(r[0]), "=r"(r[1]), "=r"(r[2]), "=r"(r[3]) : "r"(addr));
}
__device__ __forceinline__ void ldsm_x4t(uint32_t* r, uint32_t addr) {
    asm volatile("ldmatrix.sync.aligned.m8n8.x4.trans.shared.b16 {%0,%1,%2,%3}, [%4];"
                 : "=r"(r[0]), "=r"(r[1]), "=r"(r[2]), "=r"(r[3]) : "r"(addr));
}

// fast hi/lo split: hi = truncated-bf16 pair (one PRMT),
// lo = exact residual packed with one cvt.rn.bf16x2.f32.
__device__ __forceinline__ uint32_t pack_bf16x2(float lo, float hi) {
    uint32_t r;
    asm("cvt.rn.bf16x2.f32 %0, %1, %2;" : "=r"(r) : "f"(hi), "f"(lo));
    return r;
}
__device__ __forceinline__ void split_pack(float a, float b, uint32_t& hi, uint32_t& lo) {
    const uint32_t au = __float_as_uint(a), bu = __float_as_uint(b);
    hi = __byte_perm(au, bu, 0x7632);
    const float la = a - __uint_as_float(au & 0xFFFF0000u);
    const float lb = b - __uint_as_float(bu & 0xFFFF0000u);
    lo = pack_bf16x2(la, lb);
}
// reconstruct float from hi/lo packed pair, half = 0 (low16) or 1 (high16)
__device__ __forceinline__ float rq(uint32_t hi, uint32_t lo, int half) {
    const uint32_t hbits = half ? (hi & 0xFFFF0000u) : (hi << 16);
    const uint32_t lbits = half ? (lo & 0xFFFF0000u) : (lo << 16);
    return __uint_as_float(hbits) + __uint_as_float(lbits);
}

// ---------------------------------------------------------------------------
// Fused kernel. Grid is c-major: blockIdx = c*NPAIR + nh, so each tile's scan
// predecessor (same nh, c-1) is exactly NPAIR blocks earlier — a full cohort
// ahead. All 64 chains advance in lockstep cohorts.
// ---------------------------------------------------------------------------
#define KH_OFF   0
#define KL_OFF   16384
#define VH_OFF   32768
#define VL_OFF   49152
#define SH_OFF   65536
#define SL_OFF   73728
#define KSC_OFF  81920
#define KSP_OFF  82176
#define LO_OFF   82432
#define FU_SMEM  82560

__global__ void __launch_bounds__(256, 2) k_fused(const float* __restrict__ Qg,
                                                  const float* __restrict__ Kg,
                                                  const float* __restrict__ Vg,
                                                  float* __restrict__ out) {
    extern __shared__ char smc[];
    const uint32_t smb = smem_u32(smc);
    float* ksC = (float*)(smc + KSC_OFF);
    float* ksP = (float*)(smc + KSP_OFF);
    volatile int* s_lo = (volatile int*)(smc + LO_OFF);

    // c-major decomposition
    const int c  = blockIdx.x >> 6;         // chunk index 0..63
    const int nh = blockIdx.x & (NPAIR - 1);
    const int lt = nh * NCH + c;            // logical tile id for scan arrays
    const int h  = nh & (HEADS - 1);
    const int n  = nh >> 4;
    const int tid = threadIdx.x;
    const int wid = tid >> 5;
    const int lid = tid & 31;

    if (tid < EDIM) ksC[tid] = 0.f;

    const size_t base = (((size_t)n * LSEQ + (size_t)c * CHK) * HEADS + h) * EDIM;

    // triangular (output) warp coords
    const int rb  = (wid < 4) ? wid : 11 - wid;
    const int m0  = rb * 16;
    const int gi  = lid & 7;
    const int grp = lid >> 3;
    const int g1  = grp & 1;
    const int q2  = grp >> 1;
    const int r0  = m0 + (lid >> 2);
    const int r1  = r0 + 8;
    // S-MMA warp coords
    const int p_mrow  = (wid & 3) * 16;
    const int p_nhalf = (wid >> 2) * 32;

    // ---- stage K (featmap, hi/lo), V (hi/lo); accumulate ksum partials ----
    float ksr[4] = {0.f, 0.f, 0.f, 0.f};
    const int c4 = (tid & 15) << 2;
    #pragma unroll
    for (int i = 0; i < 8; i++) {
        const int p   = tid + i * 256;
        const int row = p >> 4;
        const size_t g = base + (size_t)row * ROWSTR + c4;
        const float4 kv = __ldcs((const float4*)(Kg + g));
        const float4 vv = __ldcs((const float4*)(Vg + g));
        const float kf[4] = {featmap(kv.x), featmap(kv.y), featmap(kv.z), featmap(kv.w)};
        #pragma unroll
        for (int j = 0; j < 4; j++) ksr[j] += kf[j];
        const uint32_t x = sw((uint32_t)(row * 128 + c4 * 2));
        uint32_t h01, l01, h23, l23;
        split_pack(kf[0], kf[1], h01, l01);
        split_pack(kf[2], kf[3], h23, l23);
        *(uint2*)(smc + KH_OFF + x) = make_uint2(h01, h23);
        *(uint2*)(smc + KL_OFF + x) = make_uint2(l01, l23);
        split_pack(vv.x, vv.y, h01, l01);
        split_pack(vv.z, vv.w, h23, l23);
        *(uint2*)(smc + VH_OFF + x) = make_uint2(h01, h23);
        *(uint2*)(smc + VL_OFF + x) = make_uint2(l01, l23);
    }

    // ---- build Q fragments BEFORE bar1 (LDG latency hidden under staging) ----
    uint32_t aqh[4][4], aql[4][4];
    {
        const float* Q0 = Qg + base + (size_t)r0 * ROWSTR;
        const float* Q1 = Qg + base + (size_t)r1 * ROWSTR;
        const int cc = (lid & 3) * 2;
        #pragma unroll
        for (int t = 0; t < 4; t++) {
            const int c0 = t * 16 + cc;
            const float2 q00 = __ldcs((const float2*)(Q0 + c0));
            const float2 q10 = __ldcs((const float2*)(Q1 + c0));
            const float2 q01 = __ldcs((const float2*)(Q0 + c0 + 8));
            const float2 q11 = __ldcs((const float2*)(Q1 + c0 + 8));
            split_pack(featmap(q00.x), featmap(q00.y), aqh[t][0], aql[t][0]);
            split_pack(featmap(q10.x), featmap(q10.y), aqh[t][1], aql[t][1]);
            split_pack(featmap(q01.x), featmap(q01.y), aqh[t][2], aql[t][2]);
            split_pack(featmap(q11.x), featmap(q11.y), aqh[t][3], aql[t][3]);
        }
    }
    __syncthreads();   // bar1: K/V planes + ksC init

    // ksum_c atomics (complete by bar2)
    #pragma unroll
    for (int j = 0; j < 4; j++) {
        ksr[j] += __shfl_xor_sync(0xffffffffu, ksr[j], 16);
        if (lid < 16) atomicAdd(&ksC[c4 + j], ksr[j]);
    }

    // ---- S MMA: own S_c fragments stay in registers ----
    float C[4][4] = {};
    #pragma unroll
    for (int kk = 0; kk < CHK; kk += 16) {
        uint32_t ah[4], al[4];
        const int arow = kk + ((grp & 2) ? 8 : 0) + gi;
        const int acol = p_mrow + ((grp & 1) ? 8 : 0);
        const uint32_t ax = sw((uint32_t)(arow * 128 + acol * 2));
        ldsm_x4t(ah, smb + KH_OFF + ax);
        ldsm_x4t(al, smb + KL_OFF + ax);
        const int brow = kk + g1 * 8 + gi;
        #pragma unroll
        for (int nt = 0; nt < 4; nt += 2) {
            const uint32_t bx = sw((uint32_t)(brow * 128 + (p_nhalf + (nt + q2) * 8) * 2));
            uint32_t bh[4], bl[4];
            ldsm_x4t(bh, smb + VH_OFF + bx);
            ldsm_x4t(bl, smb + VL_OFF + bx);
            mma16816(C[nt], ah, bh);
            mma16816(C[nt], ah, bl);
            mma16816(C[nt], al, bh);
            mma16816(C[nt+1], ah, bh + 2);
            mma16816(C[nt+1], ah, bl + 2);
            mma16816(C[nt+1], al, bh + 2);
        }
    }
    __syncthreads();   // bar2: ksC atomics complete
    const float ownks = (tid < EDIM) ? ksC[tid] : 0.f;

    // ---- decoupled lookback, fragment-ordered payload ----
    float ex[4][4] = {};
    float exks = 0.f;

    if (c > 0) {
        float* A = g_agg[lt];
        #pragma unroll
        for (int nt = 0; nt < 4; nt++)
            *(float4*)&A[tid * 16 + nt * 4] =
                make_float4(C[nt][0], C[nt][1], C[nt][2], C[nt][3]);
        if (tid < EDIM) A[4096 + tid] = ownks;
        __threadfence();
        __syncthreads();
        if (tid == 0) {
            atomicExch(&g_flag[lt], 1);
            // phase A: single-thread scan back to nearest inclusive
            int lo = lt - 1;
            while (true) {
                const int f = *(volatile int*)&g_flag[lo];
                if (f == 0) { __nanosleep(100); continue; }
                if (f == 2) break;
                lo--;
            }
            __threadfence();   // order payload reads after flag observation
            *s_lo = lo;
        }
        __syncthreads();
        const int lo = *s_lo;
        // phase B: all threads sum window [lo .. lt-1] (independent loads, MLP)
        for (int j = lt - 1; j >= lo; j--) {
            const float* src = (j == lo) ? g_inc[j] : g_agg[j];
            #pragma unroll
            for (int nt = 0; nt < 4; nt++) {
                const float4 t = *(const float4*)&src[tid * 16 + nt * 4];
                ex[nt][0] += t.x; ex[nt][1] += t.y;
                ex[nt][2] += t.z; ex[nt][3] += t.w;
            }
            if (tid < EDIM) exks += src[4096 + tid];
        }
    }
    {   // publish inclusive ASAP (unblocks successors)
        float* I = g_inc[lt];
        #pragma unroll
        for (int nt = 0; nt < 4; nt++)
            *(float4*)&I[tid * 16 + nt * 4] =
                make_float4(ex[nt][0] + C[nt][0], ex[nt][1] + C[nt][1],
                            ex[nt][2] + C[nt][2], ex[nt][3] + C[nt][3]);
        if (tid < EDIM) I[4096 + tid] = exks + ownks;
        __threadfence();
        __syncthreads();
        if (tid == 0) atomicExch(&g_flag[lt], 2);
    }

    // ---- exclusive prefix -> S planes (split, swizzled, fragment-direct) ----
    {
        const int e0 = p_mrow + (lid >> 2);
        const int e1 = e0 + 8;
        #pragma unroll
        for (int nt = 0; nt < 4; nt++) {
            const int d = p_nhalf + nt * 8 + (lid & 3) * 2;
            uint32_t hi, lo;
            split_pack(ex[nt][0], ex[nt][1], hi, lo);
            *(uint32_t*)(smc + SH_OFF + sw((uint32_t)(e0 * 128 + d * 2))) = hi;
            *(uint32_t*)(smc + SL_OFF + sw((uint32_t)(e0 * 128 + d * 2))) = lo;
            split_pack(ex[nt][2], ex[nt][3], hi, lo);
            *(uint32_t*)(smc + SH_OFF + sw((uint32_t)(e1 * 128 + d * 2))) = hi;
            *(uint32_t*)(smc + SL_OFF + sw((uint32_t)(e1 * 128 + d * 2))) = lo;
        }
        if (tid < EDIM) ksP[tid] = exks;
    }
    __syncthreads();   // bar3: S planes + ksP ready

    // ---- q . ksum_prefix (reconstructed from Q fragments) ----
    float rs0 = 0.f, rs1 = 0.f;
    {
        const int cc = (lid & 3) * 2;
        #pragma unroll
        for (int t = 0; t < 4; t++) {
            const int c0 = t * 16 + cc;
            const float ka = ksP[c0],     kb = ksP[c0 + 1];
            const float kc = ksP[c0 + 8], kd = ksP[c0 + 9];
            rs0 += rq(aqh[t][0], aql[t][0], 0) * ka + rq(aqh[t][0], aql[t][0], 1) * kb
                 + rq(aqh[t][2], aql[t][2], 0) * kc + rq(aqh[t][2], aql[t][2], 1) * kd;
            rs1 += rq(aqh[t][1], aql[t][1], 0) * ka + rq(aqh[t][1], aql[t][1], 1) * kb
                 + rq(aqh[t][3], aql[t][3], 0) * kc + rq(aqh[t][3], aql[t][3], 1) * kd;
        }
    }

    float C2[8][4] = {};

    // ---- triangular: for each 16-col group jg <= rb: MMA1 -> split -> MMA2 ----
    for (int jg = 0; jg <= rb; jg++) {
        float Ct[2][4] = {};
        #pragma unroll
        for (int t = 0; t < 4; t++) {
            const uint32_t bx =
                sw((uint32_t)((jg * 16 + q2 * 8 + gi) * 128 + (t * 16 + g1 * 8) * 2));
            uint32_t bh[4], bl[4];
            ldsm_x4(bh, smb + KH_OFF + bx);
            ldsm_x4(bl, smb + KL_OFF + bx);
            mma16816(Ct[0], aqh[t], bh);
            mma16816(Ct[0], aqh[t], bl);
            mma16816(Ct[0], aql[t], bh);
            mma16816(Ct[1], aqh[t], bh + 2);
            mma16816(Ct[1], aqh[t], bl + 2);
            mma16816(Ct[1], aql[t], bh + 2);
        }
        float s00 = Ct[0][0], s01 = Ct[0][1], s02 = Ct[0][2], s03 = Ct[0][3];
        float s10 = Ct[1][0], s11 = Ct[1][1], s12 = Ct[1][2], s13 = Ct[1][3];
        if (jg == rb) {   // diagonal block: causal mask
            const int cA = jg * 16 + (lid & 3) * 2;
            const int cB = cA + 8;
            s00 = (cA     <= r0) ? s00 : 0.f;
            s01 = (cA + 1 <= r0) ? s01 : 0.f;
            s02 = (cA     <= r1) ? s02 : 0.f;
            s03 = (cA + 1 <= r1) ? s03 : 0.f;
            s10 = (cB     <= r0) ? s10 : 0.f;
            s11 = (cB + 1 <= r0) ? s11 : 0.f;
            s12 = (cB     <= r1) ? s12 : 0.f;
            s13 = (cB + 1 <= r1) ? s13 : 0.f;
        }
        rs0 += s00 + s01 + s10 + s11;
        rs1 += s02 + s03 + s12 + s13;
        uint32_t a2h[4], a2l[4];
        split_pack(s00, s01, a2h[0], a2l[0]);
        split_pack(s02, s03, a2h[1], a2l[1]);
        split_pack(s10, s11, a2h[2], a2l[2]);
        split_pack(s12, s13, a2h[3], a2l[3]);
        const int brow = jg * 16 + g1 * 8 + gi;
        #pragma unroll
        for (int nt = 0; nt < 8; nt += 2) {
            const uint32_t bx = sw((uint32_t)(brow * 128 + (nt + q2) * 16));
            uint32_t bh[4], bl[4];
            ldsm_x4t(bh, smb + VH_OFF + bx);
            ldsm_x4t(bl, smb + VL_OFF + bx);
            mma16816(C2[nt], a2h, bh);
            mma16816(C2[nt], a2h, bl);
            mma16816(C2[nt], a2l, bh);
            mma16816(C2[nt+1], a2h, bh + 2);
            mma16816(C2[nt+1], a2h, bl + 2);
            mma16816(C2[nt+1], a2l, bh + 2);
        }
    }
    rs0 += __shfl_xor_sync(0xffffffffu, rs0, 1);
    rs0 += __shfl_xor_sync(0xffffffffu, rs0, 2);
    rs1 += __shfl_xor_sync(0xffffffffu, rs1, 1);
    rs1 += __shfl_xor_sync(0xffffffffu, rs1, 2);
    const float z0 = 1.f / (rs0 + 1e-6f);
    const float z1 = 1.f / (rs1 + 1e-6f);

    // ---- MMA3: C2 += Qf @ Sprefix ----
    #pragma unroll
    for (int t = 0; t < 4; t++) {
        const int brow = t * 16 + g1 * 8 + gi;
        #pragma unroll
        for (int nt = 0; nt < 8; nt += 2) {
            const uint32_t bx = sw((uint32_t)(brow * 128 + (nt + q2) * 16));
            uint32_t bh[4], bl[4];
            ldsm_x4t(bh, smb + SH_OFF + bx);
            ldsm_x4t(bl, smb + SL_OFF + bx);
            mma16816(C2[nt], aqh[t], bh);
            mma16816(C2[nt], aqh[t], bl);
            mma16816(C2[nt], aql[t], bh);
            mma16816(C2[nt+1], aqh[t], bh + 2);
            mma16816(C2[nt+1], aqh[t], bl + 2);
            mma16816(C2[nt+1], aql[t], bh + 2);
        }
    }

    // ---- epilogue: scale in regs, direct STG ----
    {
        const size_t obase = (((size_t)n * LSEQ + (size_t)c * CHK) * HEADS + h) * DDIM;
        float* O0 = out + obase + (size_t)r0 * ROWSTR;
        float* O1 = out + obase + (size_t)r1 * ROWSTR;
        const int cc = (lid & 3) * 2;
        #pragma unroll
        for (int nt = 0; nt < 8; nt++) {
            const int cb = nt * 8 + cc;
            *(float2*)(O0 + cb) = make_float2(C2[nt][0] * z0, C2[nt][1] * z0);
            *(float2*)(O1 + cb) = make_float2(C2[nt][2] * z1, C2[nt][3] * z1);
        }
    }
}

// ---------------------------------------------------------------------------
extern "C" void kernel_launch(void* const* d_in, const int* in_sizes, int n_in,
                              void* d_out, int out_size) {
    const float* Q = (const float*)d_in[0];
    const float* K = (const float*)d_in[1];
    const float* V = (const float*)d_in[2];
    float* out = (float*)d_out;

    cudaFuncSetAttribute(k_fused, cudaFuncAttributeMaxDynamicSharedMemorySize, FU_SMEM);
    k_fused<<<NTILE, 256, FU_SMEM>>>(Q, K, V, out);
}